// round 1
// baseline (speedup 1.0000x reference)
#include <cuda_runtime.h>
#include <math.h>

// Problem dimensions (fixed by setup_inputs)
#define BDIM 2
#define HDIM 32
#define SDIM 2048
#define DDIM 128
#define IDIM 128
#define FDIM 32
#define BH (BDIM*HDIM)

#define TILE_S 64
#define LIFT_SPLIT 8   // grid.z splits the 32 row-tiles per (bh,side)

// 16 MB scratch for Qlift (device global: allocation-guard safe)
static __device__ float g_qlift[BH * SDIM * FDIM];

struct __align__(16) LiftSmem {
    float W1[DDIM*IDIM];   // 64 KB
    float W2[IDIM*IDIM];   // 64 KB
    float W3[IDIM*FDIM];   // 16 KB
    float b1[IDIM];
    float b2[IDIM];
    float b3[FDIM];
    float X[TILE_S*DDIM];  // 32 KB (input tile, reused for H2)
    float Hb[TILE_S*IDIM]; // 32 KB (H1)
};

__device__ __forceinline__ float fast_sigmoid(float x) {
    return __fdividef(1.0f, 1.0f + __expf(-x));
}

// [64,128] = silu([64,128] @ [128,128] + b)   (smem -> smem)
// 16x16 threads, each computes a 4x8 register tile.
__device__ __forceinline__ void gemm_silu_64x128x128(
    const float* __restrict__ Xs, const float* __restrict__ Ws,
    const float* __restrict__ bs, float* __restrict__ Os, int tid)
{
    const int tx = tid & 15, ty = tid >> 4;
    const int r0 = ty * 4, c0 = tx * 8;

    float acc[4][8];
#pragma unroll
    for (int i = 0; i < 4; i++)
#pragma unroll
        for (int j = 0; j < 8; j++) acc[i][j] = 0.0f;

#pragma unroll 4
    for (int k = 0; k < 128; k += 4) {
        float xk[4][4];
#pragma unroll
        for (int i = 0; i < 4; i++) {
            float4 t = *reinterpret_cast<const float4*>(&Xs[(r0 + i) * 128 + k]);
            xk[i][0] = t.x; xk[i][1] = t.y; xk[i][2] = t.z; xk[i][3] = t.w;
        }
#pragma unroll
        for (int kk = 0; kk < 4; kk++) {
            float4 wa = *reinterpret_cast<const float4*>(&Ws[(k + kk) * 128 + c0]);
            float4 wb = *reinterpret_cast<const float4*>(&Ws[(k + kk) * 128 + c0 + 4]);
            float wv[8] = {wa.x, wa.y, wa.z, wa.w, wb.x, wb.y, wb.z, wb.w};
#pragma unroll
            for (int i = 0; i < 4; i++)
#pragma unroll
                for (int j = 0; j < 8; j++)
                    acc[i][j] = fmaf(xk[i][kk], wv[j], acc[i][j]);
        }
    }

#pragma unroll
    for (int i = 0; i < 4; i++) {
#pragma unroll
        for (int j = 0; j < 8; j++) {
            const int c = c0 + j;
            float v = acc[i][j] + bs[c];
            v = v * fast_sigmoid(v);            // silu
            Os[(r0 + i) * 128 + c] = v;
        }
    }
}

// out[64,32] = tanh([64,128] @ [128,32] + b)   (smem -> global)
// 16x16 threads: each computes 4 rows x 2 cols.
__device__ __forceinline__ void gemm_tanh_64x32x128(
    const float* __restrict__ Hs, const float* __restrict__ Ws,
    const float* __restrict__ bs, float* __restrict__ outg, int tid)
{
    const int tx = tid & 15, ty = tid >> 4;
    const int c0 = tx * 2, r0 = ty * 4;

    float acc[4][2];
#pragma unroll
    for (int i = 0; i < 4; i++) { acc[i][0] = 0.0f; acc[i][1] = 0.0f; }

#pragma unroll 4
    for (int k = 0; k < 128; k += 4) {
        float xk[4][4];
#pragma unroll
        for (int i = 0; i < 4; i++) {
            float4 t = *reinterpret_cast<const float4*>(&Hs[(r0 + i) * 128 + k]);
            xk[i][0] = t.x; xk[i][1] = t.y; xk[i][2] = t.z; xk[i][3] = t.w;
        }
#pragma unroll
        for (int kk = 0; kk < 4; kk++) {
            float2 w = *reinterpret_cast<const float2*>(&Ws[(k + kk) * FDIM + c0]);
#pragma unroll
            for (int i = 0; i < 4; i++) {
                acc[i][0] = fmaf(xk[i][kk], w.x, acc[i][0]);
                acc[i][1] = fmaf(xk[i][kk], w.y, acc[i][1]);
            }
        }
    }

#pragma unroll
    for (int i = 0; i < 4; i++) {
        float2 o;
        o.x = tanhf(acc[i][0] + bs[c0]);
        o.y = tanhf(acc[i][1] + bs[c0 + 1]);
        *reinterpret_cast<float2*>(&outg[(size_t)(r0 + i) * FDIM + c0]) = o;
    }
}

// One block per (bh, side, chunk). Weights resident in smem, loop over row tiles.
__global__ void __launch_bounds__(256, 1) lift_kernel(
    const float* __restrict__ Kin, const float* __restrict__ Qin,
    const float* __restrict__ wk1, const float* __restrict__ bk1,
    const float* __restrict__ wk2, const float* __restrict__ bk2,
    const float* __restrict__ wk3, const float* __restrict__ bk3,
    const float* __restrict__ wq1, const float* __restrict__ bq1,
    const float* __restrict__ wq2, const float* __restrict__ bq2,
    const float* __restrict__ wq3, const float* __restrict__ bq3,
    float* __restrict__ klift)
{
    extern __shared__ float sraw[];
    LiftSmem* sm = reinterpret_cast<LiftSmem*>(sraw);
    const int tid = threadIdx.x;
    const int bh = blockIdx.x;
    const int side = blockIdx.y;
    const int chunk = blockIdx.z;
    const int h = bh & (HDIM - 1);

    const float *Xg, *w1, *w2, *w3, *b1, *b2, *b3;
    float* outg;
    if (side == 0) {
        Xg = Kin; w1 = wk1; w2 = wk2; w3 = wk3; b1 = bk1; b2 = bk2; b3 = bk3;
        outg = klift;
    } else {
        Xg = Qin; w1 = wq1; w2 = wq2; w3 = wq3; b1 = bq1; b2 = bq2; b3 = bq3;
        outg = g_qlift;
    }
    Xg   += (size_t)bh * SDIM * DDIM;
    outg += (size_t)bh * SDIM * FDIM;
    w1 += (size_t)h * DDIM * IDIM;
    w2 += (size_t)h * IDIM * IDIM;
    w3 += (size_t)h * IDIM * FDIM;
    b1 += h * IDIM; b2 += h * IDIM; b3 += h * FDIM;

    // Load weights + biases into smem (vectorized, coalesced)
    for (int i = tid; i < DDIM * IDIM / 4; i += 256)
        reinterpret_cast<float4*>(sm->W1)[i] = reinterpret_cast<const float4*>(w1)[i];
    for (int i = tid; i < IDIM * IDIM / 4; i += 256)
        reinterpret_cast<float4*>(sm->W2)[i] = reinterpret_cast<const float4*>(w2)[i];
    for (int i = tid; i < IDIM * FDIM / 4; i += 256)
        reinterpret_cast<float4*>(sm->W3)[i] = reinterpret_cast<const float4*>(w3)[i];
    if (tid < IDIM) { sm->b1[tid] = b1[tid]; sm->b2[tid] = b2[tid]; }
    if (tid < FDIM) sm->b3[tid] = b3[tid];
    __syncthreads();

    const int tilesPer = (SDIM / TILE_S) / LIFT_SPLIT;  // 4
    for (int t = chunk * tilesPer; t < (chunk + 1) * tilesPer; ++t) {
        const int row0 = t * TILE_S;
        const float* xsrc = Xg + (size_t)row0 * DDIM;
        for (int i = tid; i < TILE_S * DDIM / 4; i += 256)
            reinterpret_cast<float4*>(sm->X)[i] = reinterpret_cast<const float4*>(xsrc)[i];
        __syncthreads();
        gemm_silu_64x128x128(sm->X,  sm->W1, sm->b1, sm->Hb, tid);   // H1
        __syncthreads();
        gemm_silu_64x128x128(sm->Hb, sm->W2, sm->b2, sm->X,  tid);   // H2 (reuse X)
        __syncthreads();
        gemm_tanh_64x32x128(sm->X, sm->W3, sm->b3, outg + (size_t)row0 * FDIM, tid);
        __syncthreads();  // before next tile overwrites X
    }
}

// scores[bh, t, s] = sigmoid(Qlift . Klift), causal (s <= t), else exact 0.
// 128x128 output tile per block. Upper-triangle tiles: pure zero-fill.
__global__ void __launch_bounds__(256, 2) scores_kernel(
    const float* __restrict__ klift, float* __restrict__ out)
{
    const int tid = threadIdx.x;
    const int ts = blockIdx.x, tq = blockIdx.y, bh = blockIdx.z;
    float* obase = out + ((size_t)bh * SDIM + (size_t)tq * 128) * SDIM + (size_t)ts * 128;

    if (ts > tq) {  // fully masked tile -> zeros
        const float4 z = make_float4(0.f, 0.f, 0.f, 0.f);
        for (int i = tid; i < 128 * 32; i += 256) {
            const int r = i >> 5, c = i & 31;
            reinterpret_cast<float4*>(obase + (size_t)r * SDIM)[c] = z;
        }
        return;
    }

    __shared__ float sQ[FDIM][132];  // transposed [k][t], padded
    __shared__ float sK[FDIM][132];  // transposed [k][s], padded
    const float* qp = g_qlift + ((size_t)bh * SDIM + (size_t)tq * 128) * FDIM;
    const float* kp = klift   + ((size_t)bh * SDIM + (size_t)ts * 128) * FDIM;
    for (int i = tid; i < 128 * FDIM; i += 256) {
        const int r = i >> 5, f = i & 31;
        sQ[f][r] = qp[i];
        sK[f][r] = kp[i];
    }
    __syncthreads();

    const int tx = tid & 15, ty = tid >> 4;
    const int t0 = ty * 8, s0 = tx * 8;
    float acc[8][8];
#pragma unroll
    for (int i = 0; i < 8; i++)
#pragma unroll
        for (int j = 0; j < 8; j++) acc[i][j] = 0.0f;

#pragma unroll 8
    for (int k = 0; k < FDIM; k++) {
        float4 qa = *reinterpret_cast<const float4*>(&sQ[k][t0]);
        float4 qb = *reinterpret_cast<const float4*>(&sQ[k][t0 + 4]);
        float4 ka = *reinterpret_cast<const float4*>(&sK[k][s0]);
        float4 kb = *reinterpret_cast<const float4*>(&sK[k][s0 + 4]);
        float qv[8] = {qa.x, qa.y, qa.z, qa.w, qb.x, qb.y, qb.z, qb.w};
        float kv[8] = {ka.x, ka.y, ka.z, ka.w, kb.x, kb.y, kb.z, kb.w};
#pragma unroll
        for (int i = 0; i < 8; i++)
#pragma unroll
            for (int j = 0; j < 8; j++)
                acc[i][j] = fmaf(qv[i], kv[j], acc[i][j]);
    }

    const bool diag = (ts == tq);
#pragma unroll
    for (int i = 0; i < 8; i++) {
        float vout[8];
#pragma unroll
        for (int j = 0; j < 8; j++) {
            float v = fast_sigmoid(acc[i][j]);
            if (diag && (s0 + j) > (t0 + i)) v = 0.0f;  // causal mask -> exact 0
            vout[j] = v;
        }
        float4* dst = reinterpret_cast<float4*>(obase + (size_t)(t0 + i) * SDIM + s0);
        dst[0] = make_float4(vout[0], vout[1], vout[2], vout[3]);
        dst[1] = make_float4(vout[4], vout[5], vout[6], vout[7]);
    }
}

extern "C" void kernel_launch(void* const* d_in, const int* in_sizes, int n_in,
                              void* d_out, int out_size)
{
    const float* K   = (const float*)d_in[0];
    const float* Q   = (const float*)d_in[1];
    const float* wk1 = (const float*)d_in[2];
    const float* bk1 = (const float*)d_in[3];
    const float* wk2 = (const float*)d_in[4];
    const float* bk2 = (const float*)d_in[5];
    const float* wk3 = (const float*)d_in[6];
    const float* bk3 = (const float*)d_in[7];
    const float* wq1 = (const float*)d_in[8];
    const float* bq1 = (const float*)d_in[9];
    const float* wq2 = (const float*)d_in[10];
    const float* bq2 = (const float*)d_in[11];
    const float* wq3 = (const float*)d_in[12];
    const float* bq3 = (const float*)d_in[13];

    float* out   = (float*)d_out;
    float* klift = out + (size_t)BH * SDIM * SDIM;  // tuple: (scores, Klift)

    cudaFuncSetAttribute(lift_kernel, cudaFuncAttributeMaxDynamicSharedMemorySize,
                         (int)sizeof(LiftSmem));

    lift_kernel<<<dim3(BH, 2, LIFT_SPLIT), 256, sizeof(LiftSmem)>>>(
        K, Q, wk1, bk1, wk2, bk2, wk3, bk3,
        wq1, bq1, wq2, bq2, wq3, bq3, klift);

    scores_kernel<<<dim3(SDIM / 128, SDIM / 128, BH), 256>>>(klift, out);
}

// round 2
// speedup vs baseline: 1.0386x; 1.0386x over previous
#include <cuda_runtime.h>
#include <math.h>

// Problem dimensions (fixed by setup_inputs)
#define BDIM 2
#define HDIM 32
#define SDIM 2048
#define DDIM 128
#define IDIM 128
#define FDIM 32
#define BH (BDIM*HDIM)

#define TILE_S 64
#define LIFT_SPLIT 8   // grid.z splits the 32 row-tiles per (bh,side)

typedef unsigned long long ull;

// 16 MB scratch for Qlift (device global: allocation-guard safe)
static __device__ float g_qlift[BH * SDIM * FDIM];

struct __align__(16) LiftSmem {
    float W1[DDIM*IDIM];   // 64 KB
    float W2[IDIM*IDIM];   // 64 KB
    float W3[IDIM*FDIM];   // 16 KB
    float b1[IDIM];
    float b2[IDIM];
    float b3[FDIM];
    float X[TILE_S*DDIM];  // 32 KB (input tile, reused for H2)
    float Hb[TILE_S*IDIM]; // 32 KB (H1)
};

// ---------- packed f32x2 helpers (Blackwell FFMA2 — only reachable via PTX) ----
__device__ __forceinline__ ull pack2b(float x) {           // broadcast scalar -> pair
    ull r; asm("mov.b64 %0, {%1, %1};" : "=l"(r) : "f"(x)); return r;
}
__device__ __forceinline__ ull fma2(ull a, ull b, ull c) { // d = a*b + c  (2 lanes)
    ull d; asm("fma.rn.f32x2 %0, %1, %2, %3;" : "=l"(d) : "l"(a), "l"(b), "l"(c));
    return d;
}
__device__ __forceinline__ float2 unpk(ull v) {
    float lo, hi; asm("mov.b64 {%0, %1}, %2;" : "=f"(lo), "=f"(hi) : "l"(v));
    return make_float2(lo, hi);
}

// precise-ish sigmoid (EX2 + RCP): used for final scores
__device__ __forceinline__ float fast_sigmoid(float x) {
    return __fdividef(1.0f, 1.0f + __expf(-x));
}
// 1-MUFU sigmoid via tanh.approx: used only inside SiLU (hidden layers)
__device__ __forceinline__ float sigmoid_t(float x) {
    float t; asm("tanh.approx.f32 %0, %1;" : "=f"(t) : "f"(x * 0.5f));
    return fmaf(t, 0.5f, 0.5f);
}

// [64,128] = silu([64,128] @ [128,128] + b)   (smem -> smem), FFMA2 inner loop.
// 16x16 threads, each computes a 4x8 register tile (stored as 4x4 f32x2 pairs).
__device__ __forceinline__ void gemm_silu_64x128x128(
    const float* __restrict__ Xs, const float* __restrict__ Ws,
    const float* __restrict__ bs, float* __restrict__ Os, int tid)
{
    const int tx = tid & 15, ty = tid >> 4;
    const int r0 = ty * 4, c0 = tx * 8;

    ull acc[4][4];
#pragma unroll
    for (int i = 0; i < 4; i++)
#pragma unroll
        for (int j = 0; j < 4; j++) acc[i][j] = 0ull;

#pragma unroll 4
    for (int k = 0; k < 128; k += 4) {
        float xk[4][4];
#pragma unroll
        for (int i = 0; i < 4; i++) {
            float4 t = *reinterpret_cast<const float4*>(&Xs[(r0 + i) * 128 + k]);
            xk[i][0] = t.x; xk[i][1] = t.y; xk[i][2] = t.z; xk[i][3] = t.w;
        }
#pragma unroll
        for (int kk = 0; kk < 4; kk++) {
            const ulonglong2* wp =
                reinterpret_cast<const ulonglong2*>(&Ws[(k + kk) * 128 + c0]);
            ulonglong2 wA = wp[0], wB = wp[1];
            ull wv[4] = {wA.x, wA.y, wB.x, wB.y};
#pragma unroll
            for (int i = 0; i < 4; i++) {
                ull xb = pack2b(xk[i][kk]);
#pragma unroll
                for (int j = 0; j < 4; j++)
                    acc[i][j] = fma2(xb, wv[j], acc[i][j]);
            }
        }
    }

#pragma unroll
    for (int i = 0; i < 4; i++) {
        float v[8];
#pragma unroll
        for (int j = 0; j < 4; j++) {
            float2 p = unpk(acc[i][j]);
            const int c = c0 + 2 * j;
            float a = p.x + bs[c];
            float b = p.y + bs[c + 1];
            v[2*j]   = a * sigmoid_t(a);   // silu
            v[2*j+1] = b * sigmoid_t(b);
        }
        float4* dst = reinterpret_cast<float4*>(&Os[(r0 + i) * 128 + c0]);
        dst[0] = make_float4(v[0], v[1], v[2], v[3]);
        dst[1] = make_float4(v[4], v[5], v[6], v[7]);
    }
}

// out[64,32] = tanh([64,128] @ [128,32] + b)   (smem -> global), small: scalar FFMA.
__device__ __forceinline__ void gemm_tanh_64x32x128(
    const float* __restrict__ Hs, const float* __restrict__ Ws,
    const float* __restrict__ bs, float* __restrict__ outg, int tid)
{
    const int tx = tid & 15, ty = tid >> 4;
    const int c0 = tx * 2, r0 = ty * 4;

    float acc[4][2];
#pragma unroll
    for (int i = 0; i < 4; i++) { acc[i][0] = 0.0f; acc[i][1] = 0.0f; }

#pragma unroll 4
    for (int k = 0; k < 128; k += 4) {
        float xk[4][4];
#pragma unroll
        for (int i = 0; i < 4; i++) {
            float4 t = *reinterpret_cast<const float4*>(&Hs[(r0 + i) * 128 + k]);
            xk[i][0] = t.x; xk[i][1] = t.y; xk[i][2] = t.z; xk[i][3] = t.w;
        }
#pragma unroll
        for (int kk = 0; kk < 4; kk++) {
            float2 w = *reinterpret_cast<const float2*>(&Ws[(k + kk) * FDIM + c0]);
#pragma unroll
            for (int i = 0; i < 4; i++) {
                acc[i][0] = fmaf(xk[i][kk], w.x, acc[i][0]);
                acc[i][1] = fmaf(xk[i][kk], w.y, acc[i][1]);
            }
        }
    }

#pragma unroll
    for (int i = 0; i < 4; i++) {
        float2 o;
        o.x = tanhf(acc[i][0] + bs[c0]);          // precise tanh on final output
        o.y = tanhf(acc[i][1] + bs[c0 + 1]);
        *reinterpret_cast<float2*>(&outg[(size_t)(r0 + i) * FDIM + c0]) = o;
    }
}

// One block per (bh, side, chunk). Weights resident in smem, loop over row tiles.
__global__ void __launch_bounds__(256, 1) lift_kernel(
    const float* __restrict__ Kin, const float* __restrict__ Qin,
    const float* __restrict__ wk1, const float* __restrict__ bk1,
    const float* __restrict__ wk2, const float* __restrict__ bk2,
    const float* __restrict__ wk3, const float* __restrict__ bk3,
    const float* __restrict__ wq1, const float* __restrict__ bq1,
    const float* __restrict__ wq2, const float* __restrict__ bq2,
    const float* __restrict__ wq3, const float* __restrict__ bq3,
    float* __restrict__ klift)
{
    extern __shared__ float sraw[];
    LiftSmem* sm = reinterpret_cast<LiftSmem*>(sraw);
    const int tid = threadIdx.x;
    const int bh = blockIdx.x;
    const int side = blockIdx.y;
    const int chunk = blockIdx.z;
    const int h = bh & (HDIM - 1);

    const float *Xg, *w1, *w2, *w3, *b1, *b2, *b3;
    float* outg;
    if (side == 0) {
        Xg = Kin; w1 = wk1; w2 = wk2; w3 = wk3; b1 = bk1; b2 = bk2; b3 = bk3;
        outg = klift;
    } else {
        Xg = Qin; w1 = wq1; w2 = wq2; w3 = wq3; b1 = bq1; b2 = bq2; b3 = bq3;
        outg = g_qlift;
    }
    Xg   += (size_t)bh * SDIM * DDIM;
    outg += (size_t)bh * SDIM * FDIM;
    w1 += (size_t)h * DDIM * IDIM;
    w2 += (size_t)h * IDIM * IDIM;
    w3 += (size_t)h * IDIM * FDIM;
    b1 += h * IDIM; b2 += h * IDIM; b3 += h * FDIM;

    // Load weights + biases into smem (vectorized, coalesced)
    for (int i = tid; i < DDIM * IDIM / 4; i += 256)
        reinterpret_cast<float4*>(sm->W1)[i] = reinterpret_cast<const float4*>(w1)[i];
    for (int i = tid; i < IDIM * IDIM / 4; i += 256)
        reinterpret_cast<float4*>(sm->W2)[i] = reinterpret_cast<const float4*>(w2)[i];
    for (int i = tid; i < IDIM * FDIM / 4; i += 256)
        reinterpret_cast<float4*>(sm->W3)[i] = reinterpret_cast<const float4*>(w3)[i];
    if (tid < IDIM) { sm->b1[tid] = b1[tid]; sm->b2[tid] = b2[tid]; }
    if (tid < FDIM) sm->b3[tid] = b3[tid];
    __syncthreads();

    const int tilesPer = (SDIM / TILE_S) / LIFT_SPLIT;  // 4
    for (int t = chunk * tilesPer; t < (chunk + 1) * tilesPer; ++t) {
        const int row0 = t * TILE_S;
        const float* xsrc = Xg + (size_t)row0 * DDIM;
        for (int i = tid; i < TILE_S * DDIM / 4; i += 256)
            reinterpret_cast<float4*>(sm->X)[i] = reinterpret_cast<const float4*>(xsrc)[i];
        __syncthreads();
        gemm_silu_64x128x128(sm->X,  sm->W1, sm->b1, sm->Hb, tid);   // H1
        __syncthreads();
        gemm_silu_64x128x128(sm->Hb, sm->W2, sm->b2, sm->X,  tid);   // H2 (reuse X)
        __syncthreads();
        gemm_tanh_64x32x128(sm->X, sm->W3, sm->b3, outg + (size_t)row0 * FDIM, tid);
        __syncthreads();  // before next tile overwrites X
    }
}

// scores[bh, t, s] = sigmoid(Qlift . Klift), causal (s <= t), else exact 0.
// 128x128 output tile per block, FFMA2 inner loop (8 rows x 4 col-pairs).
__global__ void __launch_bounds__(256, 2) scores_kernel(
    const float* __restrict__ klift, float* __restrict__ out)
{
    const int tid = threadIdx.x;
    const int ts = blockIdx.x, tq = blockIdx.y, bh = blockIdx.z;
    float* obase = out + ((size_t)bh * SDIM + (size_t)tq * 128) * SDIM + (size_t)ts * 128;

    if (ts > tq) {  // fully masked tile -> zeros
        const float4 z = make_float4(0.f, 0.f, 0.f, 0.f);
        for (int i = tid; i < 128 * 32; i += 256) {
            const int r = i >> 5, c = i & 31;
            reinterpret_cast<float4*>(obase + (size_t)r * SDIM)[c] = z;
        }
        return;
    }

    __shared__ float sQ[FDIM][132];  // transposed [k][t], padded (row = 528B, 16B-aligned)
    __shared__ float sK[FDIM][132];  // transposed [k][s], padded
    const float* qp = g_qlift + ((size_t)bh * SDIM + (size_t)tq * 128) * FDIM;
    const float* kp = klift   + ((size_t)bh * SDIM + (size_t)ts * 128) * FDIM;
    for (int i = tid; i < 128 * FDIM; i += 256) {
        const int r = i >> 5, f = i & 31;
        sQ[f][r] = qp[i];
        sK[f][r] = kp[i];
    }
    __syncthreads();

    const int tx = tid & 15, ty = tid >> 4;
    const int t0 = ty * 8, s0 = tx * 8;

    ull acc[8][4];
#pragma unroll
    for (int i = 0; i < 8; i++)
#pragma unroll
        for (int j = 0; j < 4; j++) acc[i][j] = 0ull;

#pragma unroll 8
    for (int k = 0; k < FDIM; k++) {
        const ulonglong2* kp2 = reinterpret_cast<const ulonglong2*>(&sK[k][s0]);
        ulonglong2 kA = kp2[0], kB = kp2[1];
        ull kv[4] = {kA.x, kA.y, kB.x, kB.y};
        float4 qa = *reinterpret_cast<const float4*>(&sQ[k][t0]);
        float4 qb = *reinterpret_cast<const float4*>(&sQ[k][t0 + 4]);
        float qv[8] = {qa.x, qa.y, qa.z, qa.w, qb.x, qb.y, qb.z, qb.w};
#pragma unroll
        for (int i = 0; i < 8; i++) {
            ull qx = pack2b(qv[i]);
#pragma unroll
            for (int j = 0; j < 4; j++)
                acc[i][j] = fma2(qx, kv[j], acc[i][j]);
        }
    }

    const bool diag = (ts == tq);
#pragma unroll
    for (int i = 0; i < 8; i++) {
        float vout[8];
#pragma unroll
        for (int j = 0; j < 4; j++) {
            float2 p = unpk(acc[i][j]);
            vout[2*j]   = fast_sigmoid(p.x);
            vout[2*j+1] = fast_sigmoid(p.y);
        }
        if (diag) {
#pragma unroll
            for (int j = 0; j < 8; j++)
                if ((s0 + j) > (t0 + i)) vout[j] = 0.0f;  // causal mask -> exact 0
        }
        float4* dst = reinterpret_cast<float4*>(obase + (size_t)(t0 + i) * SDIM + s0);
        dst[0] = make_float4(vout[0], vout[1], vout[2], vout[3]);
        dst[1] = make_float4(vout[4], vout[5], vout[6], vout[7]);
    }
}

extern "C" void kernel_launch(void* const* d_in, const int* in_sizes, int n_in,
                              void* d_out, int out_size)
{
    const float* K   = (const float*)d_in[0];
    const float* Q   = (const float*)d_in[1];
    const float* wk1 = (const float*)d_in[2];
    const float* bk1 = (const float*)d_in[3];
    const float* wk2 = (const float*)d_in[4];
    const float* bk2 = (const float*)d_in[5];
    const float* wk3 = (const float*)d_in[6];
    const float* bk3 = (const float*)d_in[7];
    const float* wq1 = (const float*)d_in[8];
    const float* bq1 = (const float*)d_in[9];
    const float* wq2 = (const float*)d_in[10];
    const float* bq2 = (const float*)d_in[11];
    const float* wq3 = (const float*)d_in[12];
    const float* bq3 = (const float*)d_in[13];

    float* out   = (float*)d_out;
    float* klift = out + (size_t)BH * SDIM * SDIM;  // tuple: (scores, Klift)

    cudaFuncSetAttribute(lift_kernel, cudaFuncAttributeMaxDynamicSharedMemorySize,
                         (int)sizeof(LiftSmem));

    lift_kernel<<<dim3(BH, 2, LIFT_SPLIT), 256, sizeof(LiftSmem)>>>(
        K, Q, wk1, bk1, wk2, bk2, wk3, bk3,
        wq1, bq1, wq2, bq2, wq3, bq3, klift);

    scores_kernel<<<dim3(SDIM / 128, SDIM / 128, BH), 256>>>(klift, out);
}